// round 12
// baseline (speedup 1.0000x reference)
#include <cuda_runtime.h>
#include <math.h>

#define NN 200000
#define NE 5000000
#define NBLK ((NN + 1023) / 1024)   // scan blocks (196)
#define DBINS 512                   // degree bins for counting sort

// ---- scratch ----------------------------------------------------------------
__device__ int    g_cnt[NN];      // in-degree (without self-loop)
__device__ int    g_rowptr[NN];   // CSR row start
__device__ int    g_woff[NN];     // fill cursor
__device__ int    g_bsum[NBLK + 8];
__device__ int    g_boff[NBLK + 8];
__device__ float  g_dis[NN];
__device__ int    g_esrc[NE];     // src ids bucketed by dst (norm factorized out)
__device__ int    g_hist[DBINS];  // degree histogram
__device__ int    g_bcur[DBINS];  // bin cursors
__device__ int    g_perm[NN];     // nodes sorted by degree
__device__ float  g_A[NN * 16];   // Xs ping (dis-prescaled, fp32)
__device__ float  g_B[NN * 16];   // Xs pong

// ---- zero: cnt + hist -------------------------------------------------------
__global__ void zero_kernel() {
    int i = blockIdx.x * blockDim.x + threadIdx.x;
    if (i < NN) g_cnt[i] = 0;
    if (i < DBINS) g_hist[i] = 0;
}

__global__ void count_deg_kernel(const int* __restrict__ ei) {
    int e = blockIdx.x * blockDim.x + threadIdx.x;
    if (e < NE) {
        int d = ei[NE + e];
        if ((unsigned)d < NN) atomicAdd(&g_cnt[d], 1);
    }
}

// ---- node prep: dis + degree histogram --------------------------------------
__global__ void node_prep_kernel() {
    int i = blockIdx.x * blockDim.x + threadIdx.x;
    if (i >= NN) return;
    int n = g_cnt[i];
    g_dis[i] = rsqrtf((float)(n + 1));  // self-loop included
    int b = n < DBINS ? n : DBINS - 1;
    atomicAdd(&g_hist[b], 1);
}

// ---- exclusive prefix sum of g_cnt -> g_rowptr ------------------------------
__global__ void scan1_kernel() {
    __shared__ int s[1024];
    int gid = blockIdx.x * 1024 + threadIdx.x;
    int v = (gid < NN) ? g_cnt[gid] : 0;
    s[threadIdx.x] = v;
    __syncthreads();
    for (int off = 1; off < 1024; off <<= 1) {
        int t = (threadIdx.x >= off) ? s[threadIdx.x - off] : 0;
        __syncthreads();
        s[threadIdx.x] += t;
        __syncthreads();
    }
    if (gid < NN) g_rowptr[gid] = s[threadIdx.x] - v;
    if (threadIdx.x == 1023) g_bsum[blockIdx.x] = s[1023];
}

__global__ void scan2_kernel() {          // one block, 256 threads >= NBLK
    __shared__ int s[256];
    int t = threadIdx.x;
    int v = (t < NBLK) ? g_bsum[t] : 0;
    s[t] = v;
    __syncthreads();
    for (int off = 1; off < 256; off <<= 1) {
        int u = (t >= off) ? s[t - off] : 0;
        __syncthreads();
        s[t] += u;
        __syncthreads();
    }
    if (t < NBLK) g_boff[t] = s[t] - v;   // exclusive
}

__global__ void scan3_kernel() {
    int gid = blockIdx.x * blockDim.x + threadIdx.x;
    if (gid < NN) {
        int r = g_rowptr[gid] + g_boff[gid >> 10];
        g_rowptr[gid] = r;
        g_woff[gid] = r;
    }
}

// ---- degree-bin scan + permutation fill -------------------------------------
__global__ void hist_scan_kernel() {      // one block, DBINS threads
    __shared__ int s[DBINS];
    int t = threadIdx.x;
    int v = g_hist[t];
    s[t] = v;
    __syncthreads();
    for (int off = 1; off < DBINS; off <<= 1) {
        int u = (t >= off) ? s[t - off] : 0;
        __syncthreads();
        s[t] += u;
        __syncthreads();
    }
    g_bcur[t] = s[t] - v;                 // exclusive bin start
}

__global__ void perm_fill_kernel() {
    int i = blockIdx.x * blockDim.x + threadIdx.x;
    if (i >= NN) return;
    int n = g_cnt[i];
    int b = n < DBINS ? n : DBINS - 1;
    int pos = atomicAdd(&g_bcur[b], 1);
    g_perm[pos] = i;
}

// ---- CSR fill: bucket src ids by dst ----------------------------------------
__global__ void fill_csr_kernel(const int* __restrict__ ei) {
    int e = blockIdx.x * blockDim.x + threadIdx.x;
    if (e >= NE) return;
    int s = ei[e];
    int d = ei[NE + e];
    if ((unsigned)s >= NN || (unsigned)d >= NN) return;  // trap-proof guard
    int pos = atomicAdd(&g_woff[d], 1);
    g_esrc[pos] = s;
}

// ---- layer 1 linear: Xs1 = dis * (x @ W1) -> g_A ----------------------------
__global__ void lin1_kernel(const float* __restrict__ in, const float* __restrict__ W) {
    constexpr int FIN = 12, FOUT = 16;
    __shared__ float sW[FIN * FOUT];
    int t = threadIdx.x;
    if (t < FIN * FOUT) sW[t] = W[t];
    __syncthreads();

    int i = blockIdx.x * blockDim.x + t;
    if (i >= NN) return;

    float xin[FIN];
    const float4* ip = (const float4*)(in + (size_t)i * FIN);
#pragma unroll
    for (int c = 0; c < FIN / 4; c++) {
        float4 v = ip[c];
        xin[4 * c + 0] = v.x; xin[4 * c + 1] = v.y;
        xin[4 * c + 2] = v.z; xin[4 * c + 3] = v.w;
    }
    float o[FOUT];
#pragma unroll
    for (int f = 0; f < FOUT; f++) o[f] = 0.0f;
#pragma unroll
    for (int k = 0; k < FIN; k++)
#pragma unroll
        for (int f = 0; f < FOUT; f++) o[f] = fmaf(xin[k], sW[k * FOUT + f], o[f]);

    float dv = g_dis[i];
    float4* xp = (float4*)(g_A + (size_t)i * FOUT);
#pragma unroll
    for (int c = 0; c < FOUT / 4; c++) {
        float4 v;
        v.x = o[4 * c + 0] * dv; v.y = o[4 * c + 1] * dv;
        v.z = o[4 * c + 2] * dv; v.w = o[4 * c + 3] * dv;
        xp[c] = v;
    }
}

// ---- edge aggregation of one 4-feature chunk (pure adds, no per-edge mul) ---
template <int C>
__device__ __forceinline__ float4 aggregate_chunk(const float4* __restrict__ Xc,
                                                  int i, int c) {
    int beg = g_rowptr[i];
    int n = g_cnt[i];
    float4 acc = Xc[(size_t)i * C + c];  // self term (dis-prescaled)

    const int* ep = g_esrc + beg;
    int k = 0;
    for (; k + 4 <= n; k += 4) {
        int s0 = ep[k], s1 = ep[k + 1], s2 = ep[k + 2], s3 = ep[k + 3];
        float4 v0 = Xc[(size_t)s0 * C + c];
        float4 v1 = Xc[(size_t)s1 * C + c];
        float4 v2 = Xc[(size_t)s2 * C + c];
        float4 v3 = Xc[(size_t)s3 * C + c];
        acc.x += (v0.x + v1.x) + (v2.x + v3.x);
        acc.y += (v0.y + v1.y) + (v2.y + v3.y);
        acc.z += (v0.z + v1.z) + (v2.z + v3.z);
        acc.w += (v0.w + v1.w) + (v2.w + v3.w);
    }
    for (; k < n; k++) {
        float4 v = Xc[(size_t)ep[k] * C + c];
        acc.x += v.x; acc.y += v.y; acc.z += v.z; acc.w += v.w;
    }
    return acc;
}

// ---- fused: gather L -> *dis, +b, act -> @W -> *dis -> Xs_{L+1} -------------
// Nodes processed in degree-sorted order (g_perm) for warp balance.
// C = FIN/4 chunk-threads per node (C in {2,4})
template <int FIN, int FOUT, int ACT, int INSEL>
__global__ void fused_kernel(const float* __restrict__ W, const float* __restrict__ bias) {
    constexpr int C = FIN / 4;
    constexpr int FPL = FOUT / C;   // output features per lane
    const float4* Xc = (const float4*)((INSEL == 1) ? g_A : g_B);
    float* Xout = (INSEL == 1) ? g_B : g_A;

    __shared__ float sW[FIN * FOUT];
    __shared__ float sb[16];
    int t = threadIdx.x;
    if (t < FIN * FOUT) sW[t] = W[t];
    if (t < FIN) sb[t] = bias[t];
    __syncthreads();

    int idx = blockIdx.x * blockDim.x + t;
    if (idx >= NN * C) return;    // whole-warp exits (NN*C % 32 == 0)
    int j = idx / C;
    int c = idx - j * C;
    int i = g_perm[j];            // degree-sorted node

    float4 acc = aggregate_chunk<C>(Xc, i, c);
    float dv = g_dis[i];

    // assemble full aggregate row via butterfly among the C lanes
    float row[FIN];
    row[4 * c + 0] = acc.x; row[4 * c + 1] = acc.y;
    row[4 * c + 2] = acc.z; row[4 * c + 3] = acc.w;
#pragma unroll
    for (int jj = 1; jj < C; jj++) {
        int cc = c ^ jj;
        row[4 * cc + 0] = __shfl_xor_sync(0xffffffffu, acc.x, jj);
        row[4 * cc + 1] = __shfl_xor_sync(0xffffffffu, acc.y, jj);
        row[4 * cc + 2] = __shfl_xor_sync(0xffffffffu, acc.z, jj);
        row[4 * cc + 3] = __shfl_xor_sync(0xffffffffu, acc.w, jj);
    }

    // agg = dis * row ; h = act(agg + b) ; o = h @ W[:, lane cols] ; store dis*o
    float h[FIN];
#pragma unroll
    for (int k = 0; k < FIN; k++) {
        float v = fmaf(dv, row[k], sb[k]);
        h[k] = ACT ? fmaxf(v, 0.0f) : v;
    }
    float o[FPL];
#pragma unroll
    for (int f = 0; f < FPL; f++) o[f] = 0.0f;
#pragma unroll
    for (int k = 0; k < FIN; k++)
#pragma unroll
        for (int f = 0; f < FPL; f++)
            o[f] = fmaf(h[k], sW[k * FOUT + c * FPL + f], o[f]);

    float* op = Xout + (size_t)i * FOUT + c * FPL;
#pragma unroll
    for (int f = 0; f < FPL; f++) op[f] = o[f] * dv;
}

// ---- final: gather L4 (FIN=12, C=3) -> sigmoid(dis*row + b4) -> d_out -------
__global__ void final_kernel(float4* __restrict__ out, const float* __restrict__ b4) {
    int idx = blockIdx.x * blockDim.x + threadIdx.x;
    if (idx >= NN * 3) return;
    int j = idx / 3;
    int c = idx - j * 3;
    int i = g_perm[j];

    float4 acc = aggregate_chunk<3>((const float4*)g_B, i, c);
    float dv = g_dis[i];

    float4 r;
    r.x = 1.0f / (1.0f + expf(-fmaf(dv, acc.x, b4[4 * c + 0])));
    r.y = 1.0f / (1.0f + expf(-fmaf(dv, acc.y, b4[4 * c + 1])));
    r.z = 1.0f / (1.0f + expf(-fmaf(dv, acc.z, b4[4 * c + 2])));
    r.w = 1.0f / (1.0f + expf(-fmaf(dv, acc.w, b4[4 * c + 3])));
    out[(size_t)i * 3 + c] = r;
}

// ---- launch -----------------------------------------------------------------
extern "C" void kernel_launch(void* const* d_in, const int* in_sizes, int n_in,
                              void* d_out, int out_size) {
    const float* x  = (const float*)d_in[0];
    const int*   ei = (const int*)d_in[1];   // int32 edge_index [2, E]
    const float* W1 = (const float*)d_in[2]; const float* b1 = (const float*)d_in[3];
    const float* W2 = (const float*)d_in[4]; const float* b2 = (const float*)d_in[5];
    const float* W3 = (const float*)d_in[6]; const float* b3 = (const float*)d_in[7];
    const float* W4 = (const float*)d_in[8]; const float* b4 = (const float*)d_in[9];
    float* out = (float*)d_out;

    const int BT = 256;
    const int gN = (NN + BT - 1) / BT;
    const int gE = (NE + BT - 1) / BT;

    zero_kernel<<<gN, BT>>>();
    count_deg_kernel<<<gE, BT>>>(ei);
    node_prep_kernel<<<gN, BT>>>();          // dis + degree histogram
    scan1_kernel<<<NBLK, 1024>>>();
    scan2_kernel<<<1, 256>>>();
    scan3_kernel<<<gN, BT>>>();
    hist_scan_kernel<<<1, DBINS>>>();
    perm_fill_kernel<<<gN, BT>>>();
    fill_csr_kernel<<<gE, BT>>>(ei);

    // L1 linear: Xs1 = dis * (x @ W1) -> g_A
    lin1_kernel<<<gN, BT>>>(x, W1);
    // gather L1 -> relu -> @W2 -> Xs2 (g_B)
    fused_kernel<16, 8, 1, 1><<<(NN * 4 + BT - 1) / BT, BT>>>(W2, b1);
    // gather L2 -> @W3 -> Xs3 (g_A)
    fused_kernel<8, 16, 0, 2><<<(NN * 2 + BT - 1) / BT, BT>>>(W3, b2);
    // gather L3 -> relu -> @W4 -> Xs4 (g_B)
    fused_kernel<16, 12, 1, 1><<<(NN * 4 + BT - 1) / BT, BT>>>(W4, b3);
    // gather L4 -> sigmoid -> d_out
    final_kernel<<<(NN * 3 + BT - 1) / BT, BT>>>((float4*)out, b4);
}

// round 13
// speedup vs baseline: 1.3635x; 1.3635x over previous
#include <cuda_runtime.h>
#include <math.h>

#define NN 200000
#define NE 5000000
#define NBLK ((NN + 1023) / 1024)   // scan blocks (196)

// ---- scratch ----------------------------------------------------------------
__device__ int    g_cnt[NN];      // in-degree (without self-loop)
__device__ int    g_rowptr[NN];   // CSR row start
__device__ int    g_woff[NN];     // fill cursor
__device__ int    g_bsum[NBLK + 8];
__device__ int    g_boff[NBLK + 8];
__device__ float  g_dis[NN];
__device__ int    g_esrc[NE];     // src ids bucketed by dst (norm factorized out)
__device__ float  g_A[NN * 16];   // Xs ping (dis-prescaled, fp32)
__device__ float  g_B[NN * 16];   // Xs pong

// ---- degree ----------------------------------------------------------------
__global__ void zero_cnt_kernel() {
    int i = blockIdx.x * blockDim.x + threadIdx.x;
    if (i < NN) g_cnt[i] = 0;
}

__global__ void count_deg_kernel(const int* __restrict__ ei) {
    int e = blockIdx.x * blockDim.x + threadIdx.x;
    if (e < NE) {
        int d = ei[NE + e];
        if ((unsigned)d < NN) atomicAdd(&g_cnt[d], 1);
    }
}

__global__ void dis_kernel() {
    int i = blockIdx.x * blockDim.x + threadIdx.x;
    if (i < NN) g_dis[i] = rsqrtf((float)(g_cnt[i] + 1));  // self-loop included
}

// ---- exclusive prefix sum of g_cnt -> g_rowptr ------------------------------
__global__ void scan1_kernel() {
    __shared__ int s[1024];
    int gid = blockIdx.x * 1024 + threadIdx.x;
    int v = (gid < NN) ? g_cnt[gid] : 0;
    s[threadIdx.x] = v;
    __syncthreads();
    for (int off = 1; off < 1024; off <<= 1) {
        int t = (threadIdx.x >= off) ? s[threadIdx.x - off] : 0;
        __syncthreads();
        s[threadIdx.x] += t;
        __syncthreads();
    }
    if (gid < NN) g_rowptr[gid] = s[threadIdx.x] - v;
    if (threadIdx.x == 1023) g_bsum[blockIdx.x] = s[1023];
}

__global__ void scan2_kernel() {          // one block, 256 threads >= NBLK
    __shared__ int s[256];
    int t = threadIdx.x;
    int v = (t < NBLK) ? g_bsum[t] : 0;
    s[t] = v;
    __syncthreads();
    for (int off = 1; off < 256; off <<= 1) {
        int u = (t >= off) ? s[t - off] : 0;
        __syncthreads();
        s[t] += u;
        __syncthreads();
    }
    if (t < NBLK) g_boff[t] = s[t] - v;   // exclusive
}

__global__ void scan3_kernel() {
    int gid = blockIdx.x * blockDim.x + threadIdx.x;
    if (gid < NN) {
        int r = g_rowptr[gid] + g_boff[gid >> 10];
        g_rowptr[gid] = r;
        g_woff[gid] = r;
    }
}

// ---- CSR fill: bucket src ids by dst ----------------------------------------
__global__ void fill_csr_kernel(const int* __restrict__ ei) {
    int e = blockIdx.x * blockDim.x + threadIdx.x;
    if (e >= NE) return;
    int s = ei[e];
    int d = ei[NE + e];
    if ((unsigned)s >= NN || (unsigned)d >= NN) return;  // trap-proof guard
    int pos = atomicAdd(&g_woff[d], 1);
    g_esrc[pos] = s;
}

// ---- layer 1 linear: Xs1 = dis * (x @ W1) -> g_A ----------------------------
__global__ void lin1_kernel(const float* __restrict__ in, const float* __restrict__ W) {
    constexpr int FIN = 12, FOUT = 16;
    __shared__ float sW[FIN * FOUT];
    int t = threadIdx.x;
    if (t < FIN * FOUT) sW[t] = W[t];
    __syncthreads();

    int i = blockIdx.x * blockDim.x + t;
    if (i >= NN) return;

    float xin[FIN];
    const float4* ip = (const float4*)(in + (size_t)i * FIN);
#pragma unroll
    for (int c = 0; c < FIN / 4; c++) {
        float4 v = ip[c];
        xin[4 * c + 0] = v.x; xin[4 * c + 1] = v.y;
        xin[4 * c + 2] = v.z; xin[4 * c + 3] = v.w;
    }
    float o[FOUT];
#pragma unroll
    for (int f = 0; f < FOUT; f++) o[f] = 0.0f;
#pragma unroll
    for (int k = 0; k < FIN; k++)
#pragma unroll
        for (int f = 0; f < FOUT; f++) o[f] = fmaf(xin[k], sW[k * FOUT + f], o[f]);

    float dv = g_dis[i];
    float4* xp = (float4*)(g_A + (size_t)i * FOUT);
#pragma unroll
    for (int c = 0; c < FOUT / 4; c++) {
        float4 v;
        v.x = o[4 * c + 0] * dv; v.y = o[4 * c + 1] * dv;
        v.z = o[4 * c + 2] * dv; v.w = o[4 * c + 3] * dv;
        xp[c] = v;
    }
}

// ---- edge aggregation of one 4-feature chunk (pure adds, no per-edge mul) ---
// unroll 8 for deeper MLP (8 independent row gathers in flight)
template <int C>
__device__ __forceinline__ float4 aggregate_chunk(const float4* __restrict__ Xc,
                                                  int i, int c) {
    int beg = g_rowptr[i];
    int n = g_cnt[i];
    float4 acc = Xc[(size_t)i * C + c];  // self term (dis-prescaled)

    const int* ep = g_esrc + beg;
    int k = 0;
    for (; k + 8 <= n; k += 8) {
        int s0 = ep[k],     s1 = ep[k + 1], s2 = ep[k + 2], s3 = ep[k + 3];
        int s4 = ep[k + 4], s5 = ep[k + 5], s6 = ep[k + 6], s7 = ep[k + 7];
        float4 v0 = Xc[(size_t)s0 * C + c];
        float4 v1 = Xc[(size_t)s1 * C + c];
        float4 v2 = Xc[(size_t)s2 * C + c];
        float4 v3 = Xc[(size_t)s3 * C + c];
        float4 v4 = Xc[(size_t)s4 * C + c];
        float4 v5 = Xc[(size_t)s5 * C + c];
        float4 v6 = Xc[(size_t)s6 * C + c];
        float4 v7 = Xc[(size_t)s7 * C + c];
        acc.x += ((v0.x + v1.x) + (v2.x + v3.x)) + ((v4.x + v5.x) + (v6.x + v7.x));
        acc.y += ((v0.y + v1.y) + (v2.y + v3.y)) + ((v4.y + v5.y) + (v6.y + v7.y));
        acc.z += ((v0.z + v1.z) + (v2.z + v3.z)) + ((v4.z + v5.z) + (v6.z + v7.z));
        acc.w += ((v0.w + v1.w) + (v2.w + v3.w)) + ((v4.w + v5.w) + (v6.w + v7.w));
    }
    for (; k + 4 <= n; k += 4) {
        int s0 = ep[k], s1 = ep[k + 1], s2 = ep[k + 2], s3 = ep[k + 3];
        float4 v0 = Xc[(size_t)s0 * C + c];
        float4 v1 = Xc[(size_t)s1 * C + c];
        float4 v2 = Xc[(size_t)s2 * C + c];
        float4 v3 = Xc[(size_t)s3 * C + c];
        acc.x += (v0.x + v1.x) + (v2.x + v3.x);
        acc.y += (v0.y + v1.y) + (v2.y + v3.y);
        acc.z += (v0.z + v1.z) + (v2.z + v3.z);
        acc.w += (v0.w + v1.w) + (v2.w + v3.w);
    }
    for (; k < n; k++) {
        float4 v = Xc[(size_t)ep[k] * C + c];
        acc.x += v.x; acc.y += v.y; acc.z += v.z; acc.w += v.w;
    }
    return acc;
}

// ---- fused: gather L -> *dis, +b, act -> @W -> *dis -> Xs_{L+1} -------------
// Natural node order (locality-preserving). C = FIN/4 chunk-threads per node.
// INSEL=1: read g_A write g_B ; INSEL=2: read g_B write g_A
template <int FIN, int FOUT, int ACT, int INSEL>
__global__ void fused_kernel(const float* __restrict__ W, const float* __restrict__ bias) {
    constexpr int C = FIN / 4;
    constexpr int FPL = FOUT / C;   // output features per lane
    const float4* Xc = (const float4*)((INSEL == 1) ? g_A : g_B);
    float* Xout = (INSEL == 1) ? g_B : g_A;

    __shared__ float sW[FIN * FOUT];
    __shared__ float sb[16];
    int t = threadIdx.x;
    if (t < FIN * FOUT) sW[t] = W[t];
    if (t < FIN) sb[t] = bias[t];
    __syncthreads();

    int idx = blockIdx.x * blockDim.x + t;
    if (idx >= NN * C) return;    // whole-warp exits (NN*C % 32 == 0)
    int i = idx / C;
    int c = idx - i * C;

    float4 acc = aggregate_chunk<C>(Xc, i, c);
    float dv = g_dis[i];

    // assemble full aggregate row via butterfly among the C lanes
    float row[FIN];
    row[4 * c + 0] = acc.x; row[4 * c + 1] = acc.y;
    row[4 * c + 2] = acc.z; row[4 * c + 3] = acc.w;
#pragma unroll
    for (int j = 1; j < C; j++) {
        int cc = c ^ j;
        row[4 * cc + 0] = __shfl_xor_sync(0xffffffffu, acc.x, j);
        row[4 * cc + 1] = __shfl_xor_sync(0xffffffffu, acc.y, j);
        row[4 * cc + 2] = __shfl_xor_sync(0xffffffffu, acc.z, j);
        row[4 * cc + 3] = __shfl_xor_sync(0xffffffffu, acc.w, j);
    }

    // agg = dis * row ; h = act(agg + b) ; o = h @ W[:, lane cols] ; store dis*o
    float h[FIN];
#pragma unroll
    for (int k = 0; k < FIN; k++) {
        float v = fmaf(dv, row[k], sb[k]);
        h[k] = ACT ? fmaxf(v, 0.0f) : v;
    }
    float o[FPL];
#pragma unroll
    for (int f = 0; f < FPL; f++) o[f] = 0.0f;
#pragma unroll
    for (int k = 0; k < FIN; k++)
#pragma unroll
        for (int f = 0; f < FPL; f++)
            o[f] = fmaf(h[k], sW[k * FOUT + c * FPL + f], o[f]);

    float* op = Xout + (size_t)i * FOUT + c * FPL;
#pragma unroll
    for (int f = 0; f < FPL; f++) op[f] = o[f] * dv;
}

// ---- final: gather L4 (FIN=12, C=3) -> sigmoid(dis*row + b4) -> d_out -------
__global__ void final_kernel(float4* __restrict__ out, const float* __restrict__ b4) {
    int idx = blockIdx.x * blockDim.x + threadIdx.x;
    if (idx >= NN * 3) return;
    int i = idx / 3;
    int c = idx - i * 3;

    float4 acc = aggregate_chunk<3>((const float4*)g_B, i, c);
    float dv = g_dis[i];

    float4 r;
    r.x = 1.0f / (1.0f + expf(-fmaf(dv, acc.x, b4[4 * c + 0])));
    r.y = 1.0f / (1.0f + expf(-fmaf(dv, acc.y, b4[4 * c + 1])));
    r.z = 1.0f / (1.0f + expf(-fmaf(dv, acc.z, b4[4 * c + 2])));
    r.w = 1.0f / (1.0f + expf(-fmaf(dv, acc.w, b4[4 * c + 3])));
    out[idx] = r;
}

// ---- launch -----------------------------------------------------------------
extern "C" void kernel_launch(void* const* d_in, const int* in_sizes, int n_in,
                              void* d_out, int out_size) {
    const float* x  = (const float*)d_in[0];
    const int*   ei = (const int*)d_in[1];   // int32 edge_index [2, E]
    const float* W1 = (const float*)d_in[2]; const float* b1 = (const float*)d_in[3];
    const float* W2 = (const float*)d_in[4]; const float* b2 = (const float*)d_in[5];
    const float* W3 = (const float*)d_in[6]; const float* b3 = (const float*)d_in[7];
    const float* W4 = (const float*)d_in[8]; const float* b4 = (const float*)d_in[9];
    float* out = (float*)d_out;

    const int BT = 256;
    const int gN = (NN + BT - 1) / BT;
    const int gE = (NE + BT - 1) / BT;

    zero_cnt_kernel<<<gN, BT>>>();
    count_deg_kernel<<<gE, BT>>>(ei);
    dis_kernel<<<gN, BT>>>();
    scan1_kernel<<<NBLK, 1024>>>();
    scan2_kernel<<<1, 256>>>();
    scan3_kernel<<<gN, BT>>>();
    fill_csr_kernel<<<gE, BT>>>(ei);

    // L1 linear: Xs1 = dis * (x @ W1) -> g_A
    lin1_kernel<<<gN, BT>>>(x, W1);
    // gather L1 -> relu -> @W2 -> Xs2 (g_B)
    fused_kernel<16, 8, 1, 1><<<(NN * 4 + BT - 1) / BT, BT>>>(W2, b1);
    // gather L2 -> @W3 -> Xs3 (g_A)
    fused_kernel<8, 16, 0, 2><<<(NN * 2 + BT - 1) / BT, BT>>>(W3, b2);
    // gather L3 -> relu -> @W4 -> Xs4 (g_B)
    fused_kernel<16, 12, 1, 1><<<(NN * 4 + BT - 1) / BT, BT>>>(W4, b3);
    // gather L4 -> sigmoid -> d_out
    final_kernel<<<(NN * 3 + BT - 1) / BT, BT>>>((float4*)out, b4);
}

// round 14
// speedup vs baseline: 1.3654x; 1.0014x over previous
#include <cuda_runtime.h>
#include <math.h>

#define NN 200000
#define NE 5000000
#define NEP (NE + 4 * NN)           // padded edge capacity
#define NBLK ((NN + 1023) / 1024)   // scan blocks (196)

// ---- scratch ----------------------------------------------------------------
__device__ int    g_cnt[NN];       // in-degree (without self-loop)
__device__ int    g_rowptr[NN];    // padded CSR row start (multiple of 4)
__device__ int    g_woff[NN];      // fill cursor
__device__ int    g_bsum[NBLK + 8];
__device__ int    g_boff[NBLK + 8];
__device__ float  g_dis[NN];
__device__ __align__(16) int g_esrc[NEP];  // src ids by dst, rows padded to 4 with sentinel NN
__device__ float  g_A[(NN + 1) * 16];  // Xs ping (dis-prescaled); row NN = zero sentinel
__device__ float  g_B[(NN + 1) * 16];  // Xs pong

// ---- degree ----------------------------------------------------------------
__global__ void zero_cnt_kernel() {
    int i = blockIdx.x * blockDim.x + threadIdx.x;
    if (i < NN) g_cnt[i] = 0;
    // zero the sentinel rows (row NN of both X buffers)
    if (i < 16) g_A[NN * 16 + i] = 0.0f;
    else if (i < 32) g_B[NN * 16 + (i - 16)] = 0.0f;
}

__global__ void count_deg_kernel(const int* __restrict__ ei) {
    int e = blockIdx.x * blockDim.x + threadIdx.x;
    if (e < NE) {
        int d = ei[NE + e];
        if ((unsigned)d < NN) atomicAdd(&g_cnt[d], 1);
    }
}

__global__ void dis_kernel() {
    int i = blockIdx.x * blockDim.x + threadIdx.x;
    if (i < NN) g_dis[i] = rsqrtf((float)(g_cnt[i] + 1));  // self-loop included
}

// ---- exclusive prefix sum of padded counts -> g_rowptr ----------------------
__global__ void scan1_kernel() {
    __shared__ int s[1024];
    int gid = blockIdx.x * 1024 + threadIdx.x;
    int v = (gid < NN) ? ((g_cnt[gid] + 3) & ~3) : 0;   // padded count
    s[threadIdx.x] = v;
    __syncthreads();
    for (int off = 1; off < 1024; off <<= 1) {
        int t = (threadIdx.x >= off) ? s[threadIdx.x - off] : 0;
        __syncthreads();
        s[threadIdx.x] += t;
        __syncthreads();
    }
    if (gid < NN) g_rowptr[gid] = s[threadIdx.x] - v;
    if (threadIdx.x == 1023) g_bsum[blockIdx.x] = s[1023];
}

__global__ void scan2_kernel() {          // one block, 256 threads >= NBLK
    __shared__ int s[256];
    int t = threadIdx.x;
    int v = (t < NBLK) ? g_bsum[t] : 0;
    s[t] = v;
    __syncthreads();
    for (int off = 1; off < 256; off <<= 1) {
        int u = (t >= off) ? s[t - off] : 0;
        __syncthreads();
        s[t] += u;
        __syncthreads();
    }
    if (t < NBLK) g_boff[t] = s[t] - v;   // exclusive
}

__global__ void scan3_kernel() {
    int gid = blockIdx.x * blockDim.x + threadIdx.x;
    if (gid < NN) {
        int r = g_rowptr[gid] + g_boff[gid >> 10];
        g_rowptr[gid] = r;
        g_woff[gid] = r;
    }
}

// ---- CSR fill: bucket src ids by dst ----------------------------------------
__global__ void fill_csr_kernel(const int* __restrict__ ei) {
    int e = blockIdx.x * blockDim.x + threadIdx.x;
    if (e >= NE) return;
    int s = ei[e];
    int d = ei[NE + e];
    if ((unsigned)s >= NN || (unsigned)d >= NN) return;  // trap-proof guard
    int pos = atomicAdd(&g_woff[d], 1);
    g_esrc[pos] = s;
}

// ---- pad rows to multiple of 4 with sentinel --------------------------------
__global__ void pad_csr_kernel() {
    int i = blockIdx.x * blockDim.x + threadIdx.x;
    if (i >= NN) return;
    int end = g_rowptr[i] + ((g_cnt[i] + 3) & ~3);
    for (int p = g_woff[i]; p < end; p++) g_esrc[p] = NN;  // sentinel (zero row)
}

// ---- layer 1 linear: Xs1 = dis * (x @ W1) -> g_A ----------------------------
__global__ void lin1_kernel(const float* __restrict__ in, const float* __restrict__ W) {
    constexpr int FIN = 12, FOUT = 16;
    __shared__ float sW[FIN * FOUT];
    int t = threadIdx.x;
    if (t < FIN * FOUT) sW[t] = W[t];
    __syncthreads();

    int i = blockIdx.x * blockDim.x + t;
    if (i >= NN) return;

    float xin[FIN];
    const float4* ip = (const float4*)(in + (size_t)i * FIN);
#pragma unroll
    for (int c = 0; c < FIN / 4; c++) {
        float4 v = ip[c];
        xin[4 * c + 0] = v.x; xin[4 * c + 1] = v.y;
        xin[4 * c + 2] = v.z; xin[4 * c + 3] = v.w;
    }
    float o[FOUT];
#pragma unroll
    for (int f = 0; f < FOUT; f++) o[f] = 0.0f;
#pragma unroll
    for (int k = 0; k < FIN; k++)
#pragma unroll
        for (int f = 0; f < FOUT; f++) o[f] = fmaf(xin[k], sW[k * FOUT + f], o[f]);

    float dv = g_dis[i];
    float4* xp = (float4*)(g_A + (size_t)i * FOUT);
#pragma unroll
    for (int c = 0; c < FOUT / 4; c++) {
        float4 v;
        v.x = o[4 * c + 0] * dv; v.y = o[4 * c + 1] * dv;
        v.z = o[4 * c + 2] * dv; v.w = o[4 * c + 3] * dv;
        xp[c] = v;
    }
}

// ---- edge aggregation of one 4-feature chunk --------------------------------
// Padded rows: edge ids load as int4 (4x fewer id-load issues); pads hit the
// zero sentinel row and contribute nothing. No scalar remainder.
template <int C>
__device__ __forceinline__ float4 aggregate_chunk(const float4* __restrict__ Xc,
                                                  int i, int c) {
    int beg = g_rowptr[i];                     // multiple of 4
    int pn = (g_cnt[i] + 3) & ~3;              // padded count
    float4 acc = Xc[(size_t)i * C + c];        // self term (dis-prescaled)

    const int4* ep4 = (const int4*)(g_esrc + beg);
    int nq = pn >> 2;
    int k = 0;
    for (; k + 2 <= nq; k += 2) {
        int4 q0 = ep4[k];
        int4 q1 = ep4[k + 1];
        float4 v0 = Xc[(size_t)q0.x * C + c];
        float4 v1 = Xc[(size_t)q0.y * C + c];
        float4 v2 = Xc[(size_t)q0.z * C + c];
        float4 v3 = Xc[(size_t)q0.w * C + c];
        float4 v4 = Xc[(size_t)q1.x * C + c];
        float4 v5 = Xc[(size_t)q1.y * C + c];
        float4 v6 = Xc[(size_t)q1.z * C + c];
        float4 v7 = Xc[(size_t)q1.w * C + c];
        acc.x += ((v0.x + v1.x) + (v2.x + v3.x)) + ((v4.x + v5.x) + (v6.x + v7.x));
        acc.y += ((v0.y + v1.y) + (v2.y + v3.y)) + ((v4.y + v5.y) + (v6.y + v7.y));
        acc.z += ((v0.z + v1.z) + (v2.z + v3.z)) + ((v4.z + v5.z) + (v6.z + v7.z));
        acc.w += ((v0.w + v1.w) + (v2.w + v3.w)) + ((v4.w + v5.w) + (v6.w + v7.w));
    }
    if (k < nq) {
        int4 q0 = ep4[k];
        float4 v0 = Xc[(size_t)q0.x * C + c];
        float4 v1 = Xc[(size_t)q0.y * C + c];
        float4 v2 = Xc[(size_t)q0.z * C + c];
        float4 v3 = Xc[(size_t)q0.w * C + c];
        acc.x += (v0.x + v1.x) + (v2.x + v3.x);
        acc.y += (v0.y + v1.y) + (v2.y + v3.y);
        acc.z += (v0.z + v1.z) + (v2.z + v3.z);
        acc.w += (v0.w + v1.w) + (v2.w + v3.w);
    }
    return acc;
}

// ---- fused: gather L -> *dis, +b, act -> @W -> *dis -> Xs_{L+1} -------------
// Natural node order (locality-preserving). C = FIN/4 chunk-threads per node.
// INSEL=1: read g_A write g_B ; INSEL=2: read g_B write g_A
template <int FIN, int FOUT, int ACT, int INSEL>
__global__ void fused_kernel(const float* __restrict__ W, const float* __restrict__ bias) {
    constexpr int C = FIN / 4;
    constexpr int FPL = FOUT / C;   // output features per lane
    const float4* Xc = (const float4*)((INSEL == 1) ? g_A : g_B);
    float* Xout = (INSEL == 1) ? g_B : g_A;

    __shared__ float sW[FIN * FOUT];
    __shared__ float sb[16];
    int t = threadIdx.x;
    if (t < FIN * FOUT) sW[t] = W[t];
    if (t < FIN) sb[t] = bias[t];
    __syncthreads();

    int idx = blockIdx.x * blockDim.x + t;
    if (idx >= NN * C) return;    // whole-warp exits (NN*C % 32 == 0)
    int i = idx / C;
    int c = idx - i * C;

    float4 acc = aggregate_chunk<C>(Xc, i, c);
    float dv = g_dis[i];

    // assemble full aggregate row via butterfly among the C lanes
    float row[FIN];
    row[4 * c + 0] = acc.x; row[4 * c + 1] = acc.y;
    row[4 * c + 2] = acc.z; row[4 * c + 3] = acc.w;
#pragma unroll
    for (int j = 1; j < C; j++) {
        int cc = c ^ j;
        row[4 * cc + 0] = __shfl_xor_sync(0xffffffffu, acc.x, j);
        row[4 * cc + 1] = __shfl_xor_sync(0xffffffffu, acc.y, j);
        row[4 * cc + 2] = __shfl_xor_sync(0xffffffffu, acc.z, j);
        row[4 * cc + 3] = __shfl_xor_sync(0xffffffffu, acc.w, j);
    }

    // agg = dis * row ; h = act(agg + b) ; o = h @ W[:, lane cols] ; store dis*o
    float h[FIN];
#pragma unroll
    for (int k = 0; k < FIN; k++) {
        float v = fmaf(dv, row[k], sb[k]);
        h[k] = ACT ? fmaxf(v, 0.0f) : v;
    }
    float o[FPL];
#pragma unroll
    for (int f = 0; f < FPL; f++) o[f] = 0.0f;
#pragma unroll
    for (int k = 0; k < FIN; k++)
#pragma unroll
        for (int f = 0; f < FPL; f++)
            o[f] = fmaf(h[k], sW[k * FOUT + c * FPL + f], o[f]);

    float* op = Xout + (size_t)i * FOUT + c * FPL;
#pragma unroll
    for (int f = 0; f < FPL; f++) op[f] = o[f] * dv;
}

// ---- final: gather L4 (FIN=12, C=3) -> sigmoid(dis*row + b4) -> d_out -------
__global__ void final_kernel(float4* __restrict__ out, const float* __restrict__ b4) {
    int idx = blockIdx.x * blockDim.x + threadIdx.x;
    if (idx >= NN * 3) return;
    int i = idx / 3;
    int c = idx - i * 3;

    float4 acc = aggregate_chunk<3>((const float4*)g_B, i, c);
    float dv = g_dis[i];

    float4 r;
    r.x = 1.0f / (1.0f + expf(-fmaf(dv, acc.x, b4[4 * c + 0])));
    r.y = 1.0f / (1.0f + expf(-fmaf(dv, acc.y, b4[4 * c + 1])));
    r.z = 1.0f / (1.0f + expf(-fmaf(dv, acc.z, b4[4 * c + 2])));
    r.w = 1.0f / (1.0f + expf(-fmaf(dv, acc.w, b4[4 * c + 3])));
    out[idx] = r;
}

// ---- launch -----------------------------------------------------------------
extern "C" void kernel_launch(void* const* d_in, const int* in_sizes, int n_in,
                              void* d_out, int out_size) {
    const float* x  = (const float*)d_in[0];
    const int*   ei = (const int*)d_in[1];   // int32 edge_index [2, E]
    const float* W1 = (const float*)d_in[2]; const float* b1 = (const float*)d_in[3];
    const float* W2 = (const float*)d_in[4]; const float* b2 = (const float*)d_in[5];
    const float* W3 = (const float*)d_in[6]; const float* b3 = (const float*)d_in[7];
    const float* W4 = (const float*)d_in[8]; const float* b4 = (const float*)d_in[9];
    float* out = (float*)d_out;

    const int BT = 256;
    const int gN = (NN + BT - 1) / BT;
    const int gE = (NE + BT - 1) / BT;

    zero_cnt_kernel<<<gN, BT>>>();
    count_deg_kernel<<<gE, BT>>>(ei);
    dis_kernel<<<gN, BT>>>();
    scan1_kernel<<<NBLK, 1024>>>();
    scan2_kernel<<<1, 256>>>();
    scan3_kernel<<<gN, BT>>>();
    fill_csr_kernel<<<gE, BT>>>(ei);
    pad_csr_kernel<<<gN, BT>>>();

    // L1 linear: Xs1 = dis * (x @ W1) -> g_A
    lin1_kernel<<<gN, BT>>>(x, W1);
    // gather L1 -> relu -> @W2 -> Xs2 (g_B)
    fused_kernel<16, 8, 1, 1><<<(NN * 4 + BT - 1) / BT, BT>>>(W2, b1);
    // gather L2 -> @W3 -> Xs3 (g_A)
    fused_kernel<8, 16, 0, 2><<<(NN * 2 + BT - 1) / BT, BT>>>(W3, b2);
    // gather L3 -> relu -> @W4 -> Xs4 (g_B)
    fused_kernel<16, 12, 1, 1><<<(NN * 4 + BT - 1) / BT, BT>>>(W4, b3);
    // gather L4 -> sigmoid -> d_out
    final_kernel<<<(NN * 3 + BT - 1) / BT, BT>>>((float4*)out, b4);
}

// round 15
// speedup vs baseline: 1.3842x; 1.0138x over previous
#include <cuda_runtime.h>
#include <math.h>

#define NN 200000
#define NE 5000000
#define NEP (NE + 4 * NN)           // padded edge capacity
#define NBLK ((NN + 1023) / 1024)   // scan blocks (196)

// ---- scratch ----------------------------------------------------------------
__device__ int    g_cnt[NN];       // in-degree (without self-loop)
__device__ int    g_rowptr[NN];    // padded CSR row start (multiple of 4)
__device__ int    g_woff[NN];      // fill cursor
__device__ int    g_bsum[NBLK + 8];
__device__ int    g_boff[NBLK + 8];
__device__ float  g_dis[NN];
__device__ __align__(16) int g_esrc[NEP];  // src ids by dst, rows padded to 4 with sentinel NN
__device__ float  g_A[(NN + 1) * 16];  // Y ping; row NN = zero sentinel (per active width)
__device__ float  g_B[(NN + 1) * 16];  // Y pong

// ---- zero + sentinels -------------------------------------------------------
__global__ void zero_cnt_kernel() {
    int i = blockIdx.x * blockDim.x + threadIdx.x;
    if (i < NN) g_cnt[i] = 0;
    // sentinels for this launch: A 16-wide, B 16-wide, B 8-wide
    if (i < 16) g_A[NN * 16 + i] = 0.0f;
    else if (i < 32) g_B[NN * 16 + (i - 16)] = 0.0f;
    else if (i < 40) g_B[NN * 8 + (i - 32)] = 0.0f;
}

__global__ void count_deg_kernel(const int* __restrict__ ei) {
    int e = blockIdx.x * blockDim.x + threadIdx.x;
    if (e < NE) {
        int d = ei[NE + e];
        if ((unsigned)d < NN) atomicAdd(&g_cnt[d], 1);
    }
}

// ---- scan1 (+ dis fused): exclusive prefix of padded counts -----------------
__global__ void scan1_kernel() {
    __shared__ int s[1024];
    int gid = blockIdx.x * 1024 + threadIdx.x;
    int raw = (gid < NN) ? g_cnt[gid] : 0;
    if (gid < NN) g_dis[gid] = rsqrtf((float)(raw + 1));   // self-loop included
    int v = (gid < NN) ? ((raw + 3) & ~3) : 0;             // padded count
    s[threadIdx.x] = v;
    __syncthreads();
    for (int off = 1; off < 1024; off <<= 1) {
        int t = (threadIdx.x >= off) ? s[threadIdx.x - off] : 0;
        __syncthreads();
        s[threadIdx.x] += t;
        __syncthreads();
    }
    if (gid < NN) g_rowptr[gid] = s[threadIdx.x] - v;
    if (threadIdx.x == 1023) g_bsum[blockIdx.x] = s[1023];
}

__global__ void scan2_kernel() {          // one block, 256 threads >= NBLK
    __shared__ int s[256];
    int t = threadIdx.x;
    int v = (t < NBLK) ? g_bsum[t] : 0;
    s[t] = v;
    __syncthreads();
    for (int off = 1; off < 256; off <<= 1) {
        int u = (t >= off) ? s[t - off] : 0;
        __syncthreads();
        s[t] += u;
        __syncthreads();
    }
    if (t < NBLK) g_boff[t] = s[t] - v;   // exclusive
}

__global__ void scan3_kernel() {
    int gid = blockIdx.x * blockDim.x + threadIdx.x;
    if (gid < NN) {
        int r = g_rowptr[gid] + g_boff[gid >> 10];
        g_rowptr[gid] = r;
        g_woff[gid] = r;
    }
}

// ---- CSR fill + pad ---------------------------------------------------------
__global__ void fill_csr_kernel(const int* __restrict__ ei) {
    int e = blockIdx.x * blockDim.x + threadIdx.x;
    if (e >= NE) return;
    int s = ei[e];
    int d = ei[NE + e];
    if ((unsigned)s >= NN || (unsigned)d >= NN) return;  // trap-proof guard
    int pos = atomicAdd(&g_woff[d], 1);
    g_esrc[pos] = s;
}

__global__ void pad_csr_kernel() {
    int i = blockIdx.x * blockDim.x + threadIdx.x;
    if (i >= NN) return;
    int end = g_rowptr[i] + ((g_cnt[i] + 3) & ~3);
    for (int p = g_woff[i]; p < end; p++) g_esrc[p] = NN;  // sentinel (zero row)
}

// ---- lin1: Y1 = dis * x, 12-wide padded to 16 -> g_A ------------------------
__global__ void lin1_kernel(const float* __restrict__ in) {
    int i = blockIdx.x * blockDim.x + threadIdx.x;
    if (i >= NN) return;
    float dv = g_dis[i];
    const float4* ip = (const float4*)(in + (size_t)i * 12);
    float4* yp = (float4*)(g_A + (size_t)i * 16);
#pragma unroll
    for (int c = 0; c < 3; c++) {
        float4 v = ip[c];
        v.x *= dv; v.y *= dv; v.z *= dv; v.w *= dv;
        yp[c] = v;
    }
    yp[3] = make_float4(0.0f, 0.0f, 0.0f, 0.0f);   // pad
}

// ---- edge aggregation of one 4-feature chunk (int4 edge ids, padded rows) ---
template <int C>
__device__ __forceinline__ float4 aggregate_chunk(const float4* __restrict__ Xc,
                                                  int i, int c) {
    int beg = g_rowptr[i];                     // multiple of 4
    int pn = (g_cnt[i] + 3) & ~3;              // padded count
    float4 acc = Xc[(size_t)i * C + c];        // self term (dis-prescaled)

    const int4* ep4 = (const int4*)(g_esrc + beg);
    int nq = pn >> 2;
    int k = 0;
    for (; k + 2 <= nq; k += 2) {
        int4 q0 = ep4[k];
        int4 q1 = ep4[k + 1];
        float4 v0 = Xc[(size_t)q0.x * C + c];
        float4 v1 = Xc[(size_t)q0.y * C + c];
        float4 v2 = Xc[(size_t)q0.z * C + c];
        float4 v3 = Xc[(size_t)q0.w * C + c];
        float4 v4 = Xc[(size_t)q1.x * C + c];
        float4 v5 = Xc[(size_t)q1.y * C + c];
        float4 v6 = Xc[(size_t)q1.z * C + c];
        float4 v7 = Xc[(size_t)q1.w * C + c];
        acc.x += ((v0.x + v1.x) + (v2.x + v3.x)) + ((v4.x + v5.x) + (v6.x + v7.x));
        acc.y += ((v0.y + v1.y) + (v2.y + v3.y)) + ((v4.y + v5.y) + (v6.y + v7.y));
        acc.z += ((v0.z + v1.z) + (v2.z + v3.z)) + ((v4.z + v5.z) + (v6.z + v7.z));
        acc.w += ((v0.w + v1.w) + (v2.w + v3.w)) + ((v4.w + v5.w) + (v6.w + v7.w));
    }
    if (k < nq) {
        int4 q0 = ep4[k];
        float4 v0 = Xc[(size_t)q0.x * C + c];
        float4 v1 = Xc[(size_t)q0.y * C + c];
        float4 v2 = Xc[(size_t)q0.z * C + c];
        float4 v3 = Xc[(size_t)q0.w * C + c];
        acc.x += (v0.x + v1.x) + (v2.x + v3.x);
        acc.y += (v0.y + v1.y) + (v2.y + v3.y);
        acc.z += (v0.z + v1.z) + (v2.z + v3.z);
        acc.w += (v0.w + v1.w) + (v2.w + v3.w);
    }
    return acc;
}

// ---- fused1: gather Y1 (A, 16-wide, 12 valid) -> @W1 +b1 relu -> @W2 ->
//      Y2 = dis*(h1@W2) (B, 8-wide). C=4 lanes/node, FPL=2.
__global__ void fused1_kernel(const float* __restrict__ W1, const float* __restrict__ b1,
                              const float* __restrict__ W2) {
    __shared__ float sW1[12 * 16];
    __shared__ float sW2[16 * 8];
    __shared__ float sb1[16];
    int t = threadIdx.x;
    if (t < 192) sW1[t] = W1[t];
    if (t < 128) sW2[t] = W2[t];
    if (t < 16) sb1[t] = b1[t];
    __syncthreads();

    int idx = blockIdx.x * blockDim.x + t;
    if (idx >= NN * 4) return;    // whole-warp exits
    int i = idx >> 2;
    int c = idx & 3;

    float4 acc;
    if (c == 3) acc = make_float4(0.0f, 0.0f, 0.0f, 0.0f);  // pad chunk, known zero
    else acc = aggregate_chunk<4>((const float4*)g_A, i, c);
    float dv = g_dis[i];

    // butterfly: assemble 12 valid features (chunk 3 is pad)
    float row[12];
    if (c < 3) { row[4*c] = acc.x; row[4*c+1] = acc.y; row[4*c+2] = acc.z; row[4*c+3] = acc.w; }
#pragma unroll
    for (int j = 1; j < 4; j++) {
        int cc = c ^ j;
        float rx = __shfl_xor_sync(0xffffffffu, acc.x, j);
        float ry = __shfl_xor_sync(0xffffffffu, acc.y, j);
        float rz = __shfl_xor_sync(0xffffffffu, acc.z, j);
        float rw = __shfl_xor_sync(0xffffffffu, acc.w, j);
        if (cc < 3) { row[4*cc] = rx; row[4*cc+1] = ry; row[4*cc+2] = rz; row[4*cc+3] = rw; }
    }

    // h1 = relu( (dv*row) @ W1 + b1 )  (full 16-vector per lane)
    float h1[16];
#pragma unroll
    for (int f = 0; f < 16; f++) h1[f] = sb1[f];
#pragma unroll
    for (int k = 0; k < 12; k++) {
        float a = dv * row[k];
#pragma unroll
        for (int f = 0; f < 16; f++) h1[f] = fmaf(a, sW1[k * 16 + f], h1[f]);
    }
#pragma unroll
    for (int f = 0; f < 16; f++) h1[f] = fmaxf(h1[f], 0.0f);

    // this lane's 2 output columns of W2; Y2 = dv * (h1 @ W2)
    float o0 = 0.0f, o1 = 0.0f;
#pragma unroll
    for (int k = 0; k < 16; k++) {
        o0 = fmaf(h1[k], sW2[k * 8 + 2 * c + 0], o0);
        o1 = fmaf(h1[k], sW2[k * 8 + 2 * c + 1], o1);
    }
    float* op = g_B + (size_t)i * 8 + 2 * c;
    op[0] = o0 * dv;
    op[1] = o1 * dv;
}

// ---- fused2: gather Y2 (B, 8-wide) -> h2 = agg + b2 -> Y3 = dis*h2 (A, 8-wide)
//      C=2 lanes/node, no matmul, no butterfly. Also zeroes A's 8-wide sentinel.
__global__ void fused2_kernel(const float* __restrict__ b2) {
    int idx = blockIdx.x * blockDim.x + threadIdx.x;
    if (idx == 0) {   // zero A 8-wide sentinel (Y1 in A is dead now)
        float4 z = make_float4(0.0f, 0.0f, 0.0f, 0.0f);
        ((float4*)(g_A + NN * 8))[0] = z;
        ((float4*)(g_A + NN * 8))[1] = z;
    }
    if (idx >= NN * 2) return;
    int i = idx >> 1;
    int c = idx & 1;

    float4 acc = aggregate_chunk<2>((const float4*)g_B, i, c);
    float dv = g_dis[i];
    // Y3 chunk = dv * (dv*acc + b2[chunk])
    float4 r;
    r.x = dv * fmaf(dv, acc.x, b2[4 * c + 0]);
    r.y = dv * fmaf(dv, acc.y, b2[4 * c + 1]);
    r.z = dv * fmaf(dv, acc.z, b2[4 * c + 2]);
    r.w = dv * fmaf(dv, acc.w, b2[4 * c + 3]);
    ((float4*)(g_A + (size_t)i * 8))[c] = r;
}

// ---- fused3: gather Y3 (A, 8-wide) -> @W3 +b3 relu -> @W4 ->
//      Y4 = dis*(h3@W4) (B, 16-wide, 12 valid + 4 pad). C=2, 6 cols/lane.
__global__ void fused3_kernel(const float* __restrict__ W3, const float* __restrict__ b3,
                              const float* __restrict__ W4) {
    __shared__ float sW3[8 * 16];
    __shared__ float sW4[16 * 12];
    __shared__ float sb3[16];
    int t = threadIdx.x;
    if (t < 128) sW3[t] = W3[t];
    if (t < 192) sW4[t] = W4[t];
    if (t < 16) sb3[t] = b3[t];
    __syncthreads();

    int idx = blockIdx.x * blockDim.x + t;
    if (idx >= NN * 2) return;
    int i = idx >> 1;
    int c = idx & 1;

    float4 acc = aggregate_chunk<2>((const float4*)g_A, i, c);
    float dv = g_dis[i];

    // butterfly (C=2): full 8-row
    float row[8];
    row[4*c] = acc.x; row[4*c+1] = acc.y; row[4*c+2] = acc.z; row[4*c+3] = acc.w;
    {
        int cc = c ^ 1;
        row[4*cc]   = __shfl_xor_sync(0xffffffffu, acc.x, 1);
        row[4*cc+1] = __shfl_xor_sync(0xffffffffu, acc.y, 1);
        row[4*cc+2] = __shfl_xor_sync(0xffffffffu, acc.z, 1);
        row[4*cc+3] = __shfl_xor_sync(0xffffffffu, acc.w, 1);
    }

    // h3 = relu( (dv*row) @ W3 + b3 )
    float h3[16];
#pragma unroll
    for (int f = 0; f < 16; f++) h3[f] = sb3[f];
#pragma unroll
    for (int k = 0; k < 8; k++) {
        float a = dv * row[k];
#pragma unroll
        for (int f = 0; f < 16; f++) h3[f] = fmaf(a, sW3[k * 16 + f], h3[f]);
    }
#pragma unroll
    for (int f = 0; f < 16; f++) h3[f] = fmaxf(h3[f], 0.0f);

    // this lane's 6 output columns of W4; Y4 = dv * (h3 @ W4), padded row of 16
    float o[6];
#pragma unroll
    for (int f = 0; f < 6; f++) o[f] = 0.0f;
#pragma unroll
    for (int k = 0; k < 16; k++)
#pragma unroll
        for (int f = 0; f < 6; f++)
            o[f] = fmaf(h3[k], sW4[k * 12 + 6 * c + f], o[f]);

    float* op = g_B + (size_t)i * 16 + 6 * c;
#pragma unroll
    for (int f = 0; f < 6; f++) op[f] = o[f] * dv;
    if (c == 1) {   // pad cols 12..15
        float* pp = g_B + (size_t)i * 16 + 12;
        pp[0] = 0.0f; pp[1] = 0.0f; pp[2] = 0.0f; pp[3] = 0.0f;
    }
}

// ---- final: gather Y4 (B, 16-wide, 12 valid) -> sigmoid(dv*agg + b4) -> out
__global__ void final_kernel(float4* __restrict__ out, const float* __restrict__ b4) {
    int idx = blockIdx.x * blockDim.x + threadIdx.x;
    if (idx >= NN * 4) return;
    int i = idx >> 2;
    int c = idx & 3;
    if (c == 3) return;   // pad chunk: nothing to write (no shuffles here)

    float4 acc = aggregate_chunk<4>((const float4*)g_B, i, c);
    float dv = g_dis[i];

    float4 r;
    r.x = 1.0f / (1.0f + expf(-fmaf(dv, acc.x, b4[4 * c + 0])));
    r.y = 1.0f / (1.0f + expf(-fmaf(dv, acc.y, b4[4 * c + 1])));
    r.z = 1.0f / (1.0f + expf(-fmaf(dv, acc.z, b4[4 * c + 2])));
    r.w = 1.0f / (1.0f + expf(-fmaf(dv, acc.w, b4[4 * c + 3])));
    out[(size_t)i * 3 + c] = r;
}

// ---- launch -----------------------------------------------------------------
extern "C" void kernel_launch(void* const* d_in, const int* in_sizes, int n_in,
                              void* d_out, int out_size) {
    const float* x  = (const float*)d_in[0];
    const int*   ei = (const int*)d_in[1];   // int32 edge_index [2, E]
    const float* W1 = (const float*)d_in[2]; const float* b1 = (const float*)d_in[3];
    const float* W2 = (const float*)d_in[4]; const float* b2 = (const float*)d_in[5];
    const float* W3 = (const float*)d_in[6]; const float* b3 = (const float*)d_in[7];
    const float* W4 = (const float*)d_in[8]; const float* b4 = (const float*)d_in[9];
    float* out = (float*)d_out;

    const int BT = 256;
    const int gN = (NN + BT - 1) / BT;
    const int gE = (NE + BT - 1) / BT;
    const int g2 = (NN * 2 + BT - 1) / BT;
    const int g4 = (NN * 4 + BT - 1) / BT;

    zero_cnt_kernel<<<gN, BT>>>();
    count_deg_kernel<<<gE, BT>>>(ei);
    scan1_kernel<<<NBLK, 1024>>>();          // also computes g_dis
    scan2_kernel<<<1, 256>>>();
    scan3_kernel<<<gN, BT>>>();
    fill_csr_kernel<<<gE, BT>>>(ei);
    pad_csr_kernel<<<gN, BT>>>();

    lin1_kernel<<<gN, BT>>>(x);              // Y1 = dis*x (padded 16) -> A
    fused1_kernel<<<g4, BT>>>(W1, b1, W2);   // -> Y2 (B, 8)
    fused2_kernel<<<g2, BT>>>(b2);           // -> Y3 (A, 8)
    fused3_kernel<<<g2, BT>>>(W3, b3, W4);   // -> Y4 (B, 16 padded)
    final_kernel<<<g4, BT>>>((float4*)out, b4);
}